// round 2
// baseline (speedup 1.0000x reference)
#include <cuda_runtime.h>

#define NPTS   8192
#define GAMMA_ 100.0f          // 1 / sigma^2, sigma = 0.1
#define TILE   256
#define NSPLIT 16
#define JCHUNK (NPTS / NSPLIT) // 512

__global__ void zero_kernel(float* __restrict__ out, int n) {
    int i = blockIdx.x * blockDim.x + threadIdx.x;
    if (i < n) out[i] = 0.0f;
}

__global__ __launch_bounds__(TILE)
void lddmm_kernel(const float* __restrict__ mom,
                  const float* __restrict__ x,
                  float* __restrict__ out)
{
    // Tile of j-points: [0]=x_j (xyz_), [1]=p_j (xyz_), 16B aligned -> LDS.128
    __shared__ float4 sj[TILE][2];

    const int tid = threadIdx.x;
    const int i   = blockIdx.x * TILE + tid;

    const float xi0 = x[3*i+0],   xi1 = x[3*i+1],   xi2 = x[3*i+2];
    const float pi0 = mom[3*i+0], pi1 = mom[3*i+1], pi2 = mom[3*i+2];

    float dx0 = 0.f, dx1 = 0.f, dx2 = 0.f;   // dx_i   = sum_j K_ij p_j
    float dm0 = 0.f, dm1 = 0.f, dm2 = 0.f;   // sum_j K_ij <p_i,p_j> (x_i - x_j)

    const int jbase = blockIdx.y * JCHUNK;

    for (int t = 0; t < JCHUNK; t += TILE) {
        const int j = jbase + t + tid;
        sj[tid][0] = make_float4(x[3*j+0],   x[3*j+1],   x[3*j+2],   0.f);
        sj[tid][1] = make_float4(mom[3*j+0], mom[3*j+1], mom[3*j+2], 0.f);
        __syncthreads();

        #pragma unroll 8
        for (int k = 0; k < TILE; k++) {
            const float4 xj = sj[k][0];   // broadcast, conflict-free
            const float4 pj = sj[k][1];

            const float d0 = xi0 - xj.x;
            const float d1 = xi1 - xj.y;
            const float d2 = xi2 - xj.z;
            const float r2 = d0*d0 + d1*d1 + d2*d2;

            const float Kv = __expf(-GAMMA_ * r2);        // FMUL + MUFU.EX2
            const float pd = pi0*pj.x + pi1*pj.y + pi2*pj.z;
            const float w  = Kv * pd;

            dx0 += Kv * pj.x;  dx1 += Kv * pj.y;  dx2 += Kv * pj.z;
            dm0 += w  * d0;    dm1 += w  * d1;    dm2 += w  * d2;
        }
        __syncthreads();
    }

    // dmom_i = 2*gamma * dm ; outputs: [dmom (3N) | dx (3N)]
    const float c = 2.0f * GAMMA_;
    atomicAdd(&out[3*i + 0],          c * dm0);
    atomicAdd(&out[3*i + 1],          c * dm1);
    atomicAdd(&out[3*i + 2],          c * dm2);
    atomicAdd(&out[3*NPTS + 3*i + 0], dx0);
    atomicAdd(&out[3*NPTS + 3*i + 1], dx1);
    atomicAdd(&out[3*NPTS + 3*i + 2], dx2);
}

extern "C" void kernel_launch(void* const* d_in, const int* in_sizes, int n_in,
                              void* d_out, int out_size)
{
    const float* mom = (const float*)d_in[0];   // [1, 8192, 3]
    const float* x   = (const float*)d_in[1];   // [1, 8192, 3]
    float*       out = (float*)d_out;           // [2, 8192, 3] = dmom | dx

    zero_kernel<<<(out_size + 255) / 256, 256>>>(out, out_size);

    dim3 grid(NPTS / TILE, NSPLIT);
    lddmm_kernel<<<grid, TILE>>>(mom, x, out);
}